// round 4
// baseline (speedup 1.0000x reference)
#include <cuda_runtime.h>
#include <math.h>

// Problem geometry
#define NFRAMES   160          // B*T = 8*20
#define HW        512
#define OUTW      506          // 512 - 7 + 1
#define TILE_TY   8
#define TILE_TX   128
#define H_LOAD    14           // TILE_TY + 6
#define W_LOAD    134          // TILE_TX + 6
#define XS_W      136          // padded row stride for input tiles
#define CS_W      154          // padded+skewed row stride for colsum rows
#define GRID_X    4            // ceil(506/128)
#define GRID_Y    64           // ceil(506/8)
#define NBLOCKS   (NFRAMES * GRID_Y * GRID_X)   // 40960

// Per-block partial sums: [abs, sq, ssim]
__device__ float g_scratch[NBLOCKS * 3];

__global__ __launch_bounds__(128, 5)
void ssim_tile_kernel(const float* __restrict__ gen,
                      const float* __restrict__ tgt)
{
    __shared__ float xs[H_LOAD * XS_W];
    __shared__ float ys[H_LOAD * XS_W];
    __shared__ float cs[5 * TILE_TY * CS_W];
    __shared__ float red[3][4];

    const int t  = threadIdx.x;
    const int c0 = blockIdx.x * TILE_TX;
    const int r0 = blockIdx.y * TILE_TY;
    const int f  = blockIdx.z;
    const int fbase = f * (HW * HW);

    float pabs = 0.f, psq = 0.f, pssim = 0.f;

    // ---------- Phase 1: fill tile (clamped), fused L_rec over exclusive region ----
    for (int k = t; k < H_LOAD * W_LOAD; k += 128) {
        int i = k / W_LOAD;
        int j = k - i * W_LOAD;
        int r = r0 + i; if (r > HW - 1) r = HW - 1;
        int c = c0 + j; if (c > HW - 1) c = HW - 1;
        int g = fbase + r * HW + c;
        float a = gen[g];
        float b = tgt[g];
        xs[i * XS_W + j] = a;
        ys[i * XS_W + j] = b;
        // exclusive coverage: rows [r0, r0+8) x cols [c0, c0+128) tile the 512x512
        // frame exactly once across the grid (64*8 = 512, 4*128 = 512).
        if (i < TILE_TY && j < TILE_TX) {
            float d = a - b;
            pabs += fabsf(d);
            psq = fmaf(d, d, psq);
        }
    }
    __syncthreads();

    // ---------- Phase 2: vertical 7-sums (register ring, sliding) -----------------
    for (int col = t; col < W_LOAD; col += 128) {
        float rxx[7], ryy[7];
        float sx = 0.f, sy = 0.f, sxx = 0.f, syy = 0.f, sxy = 0.f;
#pragma unroll
        for (int k = 0; k < 7; ++k) {
            float a = xs[k * XS_W + col];
            float b = ys[k * XS_W + col];
            rxx[k] = a; ryy[k] = b;
            sx += a; sy += b;
            sxx = fmaf(a, a, sxx);
            syy = fmaf(b, b, syy);
            sxy = fmaf(a, b, sxy);
        }
        const int sc = col + (col >> 3);   // skew to decorrelate stride-8 readers
        cs[(0 * TILE_TY + 0) * CS_W + sc] = sx;
        cs[(1 * TILE_TY + 0) * CS_W + sc] = sy;
        cs[(2 * TILE_TY + 0) * CS_W + sc] = sxx;
        cs[(3 * TILE_TY + 0) * CS_W + sc] = syy;
        cs[(4 * TILE_TY + 0) * CS_W + sc] = sxy;
#pragma unroll
        for (int ty = 1; ty < TILE_TY; ++ty) {
            float a  = xs[(ty + 6) * XS_W + col];
            float b  = ys[(ty + 6) * XS_W + col];
            float ao = rxx[ty - 1];
            float bo = ryy[ty - 1];
            sx += a - ao;
            sy += b - bo;
            sxx = fmaf(a, a, sxx);   sxx = fmaf(-ao, ao, sxx);
            syy = fmaf(b, b, syy);   syy = fmaf(-bo, bo, syy);
            sxy = fmaf(a, b, sxy);   sxy = fmaf(-ao, bo, sxy);
            cs[(0 * TILE_TY + ty) * CS_W + sc] = sx;
            cs[(1 * TILE_TY + ty) * CS_W + sc] = sy;
            cs[(2 * TILE_TY + ty) * CS_W + sc] = sxx;
            cs[(3 * TILE_TY + ty) * CS_W + sc] = syy;
            cs[(4 * TILE_TY + ty) * CS_W + sc] = sxy;
        }
    }
    __syncthreads();

    // ---------- Phase 3: horizontal 7-sums (register ring, sliding) + SSIM --------
    {
        const int tyEff = min(TILE_TY, OUTW - r0);
        const int txEff = min(TILE_TX, OUTW - c0);
        const int ty  = t >> 4;          // 0..7
        const int ox0 = (t & 15) * 8;    // 0..120
        const int b0 = (0 * TILE_TY + ty) * CS_W;
        const int b1 = (1 * TILE_TY + ty) * CS_W;
        const int b2 = (2 * TILE_TY + ty) * CS_W;
        const int b3 = (3 * TILE_TY + ty) * CS_W;
        const int b4 = (4 * TILE_TY + ty) * CS_W;

        float q0[7], q1[7], q2[7], q3[7], q4[7];
        float S0 = 0.f, S1 = 0.f, S2 = 0.f, S3 = 0.f, S4 = 0.f;
#pragma unroll
        for (int k = 0; k < 7; ++k) {
            int xi = ox0 + k;
            int sk = xi + (xi >> 3);
            float v;
            v = cs[b0 + sk]; q0[k] = v; S0 += v;
            v = cs[b1 + sk]; q1[k] = v; S1 += v;
            v = cs[b2 + sk]; q2[k] = v; S2 += v;
            v = cs[b3 + sk]; q3[k] = v; S3 += v;
            v = cs[b4 + sk]; q4[k] = v; S4 += v;
        }

        const float inv49 = 1.0f / 49.0f;
        const float inv48 = 1.0f / 48.0f;
        const float cnrm  = 49.0f / 48.0f;
        const float C1p   = 1.0e-4f;   // (0.01)^2  (255-scaling divided out)
        const float C2p   = 9.0e-4f;   // (0.03)^2

#pragma unroll
        for (int s = 0; s < 8; ++s) {
            if (s > 0) {
                int xi = ox0 + 6 + s;
                int sk = xi + (xi >> 3);
                S0 += cs[b0 + sk] - q0[s - 1];
                S1 += cs[b1 + sk] - q1[s - 1];
                S2 += cs[b2 + sk] - q2[s - 1];
                S3 += cs[b3 + sk] - q3[s - 1];
                S4 += cs[b4 + sk] - q4[s - 1];
            }
            int ox = ox0 + s;
            if (ty < tyEff && ox < txEff) {
                float ux  = S0 * inv49;
                float uy  = S1 * inv49;
                float ux2 = ux * ux;
                float uy2 = uy * uy;
                float uxy = ux * uy;
                float vx  = fmaf(S2, inv48, -cnrm * ux2);
                float vy  = fmaf(S3, inv48, -cnrm * uy2);
                float vxy = fmaf(S4, inv48, -cnrm * uxy);
                float num = fmaf(2.f, uxy, C1p) * fmaf(2.f, vxy, C2p);
                float den = (ux2 + uy2 + C1p) * (vx + vy + C2p);
                pssim += __fdividef(num, den);
            }
        }
    }

    // ---------- Block reduction -> scratch ---------------------------------------
#pragma unroll
    for (int off = 16; off; off >>= 1) {
        pabs  += __shfl_xor_sync(0xFFFFFFFFu, pabs,  off);
        psq   += __shfl_xor_sync(0xFFFFFFFFu, psq,   off);
        pssim += __shfl_xor_sync(0xFFFFFFFFu, pssim, off);
    }
    const int wid = t >> 5, lane = t & 31;
    if (lane == 0) { red[0][wid] = pabs; red[1][wid] = psq; red[2][wid] = pssim; }
    __syncthreads();
    if (t == 0) {
        float a = red[0][0] + red[0][1] + red[0][2] + red[0][3];
        float s = red[1][0] + red[1][1] + red[1][2] + red[1][3];
        float m = red[2][0] + red[2][1] + red[2][2] + red[2][3];
        int bid = (blockIdx.z * GRID_Y + blockIdx.y) * GRID_X + blockIdx.x;
        g_scratch[bid * 3 + 0] = a;
        g_scratch[bid * 3 + 1] = s;
        g_scratch[bid * 3 + 2] = m;
    }
}

__global__ __launch_bounds__(1024)
void finalize_kernel(const float* __restrict__ genD, int nD,
                     float* __restrict__ out)
{
    __shared__ double sm[3][32];
    double a = 0.0, s = 0.0, m = 0.0;
    for (int b = threadIdx.x; b < NBLOCKS; b += 1024) {
        a += (double)g_scratch[b * 3 + 0];
        s += (double)g_scratch[b * 3 + 1];
        m += (double)g_scratch[b * 3 + 2];
    }
#pragma unroll
    for (int off = 16; off; off >>= 1) {
        a += __shfl_xor_sync(0xFFFFFFFFu, a, off);
        s += __shfl_xor_sync(0xFFFFFFFFu, s, off);
        m += __shfl_xor_sync(0xFFFFFFFFu, m, off);
    }
    const int wid = threadIdx.x >> 5, lane = threadIdx.x & 31;
    if (lane == 0) { sm[0][wid] = a; sm[1][wid] = s; sm[2][wid] = m; }
    __syncthreads();
    if (threadIdx.x == 0) {
        double A = 0.0, S = 0.0, M = 0.0;
#pragma unroll
        for (int w = 0; w < 32; ++w) { A += sm[0][w]; S += sm[1][w]; M += sm[2][w]; }
        const double Ntot = (double)NFRAMES * HW * HW;   // 41,943,040
        double L_rec  = (A + S) / Ntot;
        double L_ssim = M / ((double)NFRAMES * OUTW * OUTW);
        double sd = 0.0;
        for (int i = 0; i < nD; ++i) sd += (double)genD[i];
        double L_adv   = -sd / (double)nD;
        double L_total = L_rec + 0.01 * (1.0 - L_ssim) + 1.0e-4 * L_adv;
        out[0] = (float)L_total;
        out[1] = (float)L_rec;
        out[2] = (float)L_ssim;
        out[3] = (float)L_adv;
    }
}

extern "C" void kernel_launch(void* const* d_in, const int* in_sizes, int n_in,
                              void* d_out, int out_size)
{
    const float* gen = (const float*)d_in[0];
    const float* tgt = (const float*)d_in[1];
    const float* gD  = (const float*)d_in[2];
    float* out = (float*)d_out;

    dim3 grid(GRID_X, GRID_Y, NFRAMES);
    ssim_tile_kernel<<<grid, 128>>>(gen, tgt);
    finalize_kernel<<<1, 1024>>>(gD, in_sizes[2], out);
}

// round 5
// speedup vs baseline: 1.4163x; 1.4163x over previous
#include <cuda_runtime.h>
#include <math.h>

// Geometry
#define NFRAMES   160          // B*T
#define HW        512
#define FRAME     (HW * HW)    // 262144
#define OUTW      506          // 512 - 7 + 1
#define STRIPS    20           // ceil(506 / 26)
#define NWARPS    (NFRAMES * STRIPS)   // 3200
#define BLOCK_T   128
#define NBLOCKS   (NWARPS / (BLOCK_T / 32))   // 800

// Per-warp partial sums: [abs, sq, ssim]
__device__ float g_scratch[NWARPS * 3];

__device__ __forceinline__ float hsum7(float s) {
    // 7-tap sliding sum across lanes: result_l = s_l + ... + s_{l+6}
    float t1 = s + __shfl_down_sync(0xFFFFFFFFu, s, 1);   // 2-sum
    float t2 = t1 + __shfl_down_sync(0xFFFFFFFFu, t1, 2); // 4-sum
    float r  = t2 + __shfl_down_sync(0xFFFFFFFFu, t1, 4); // 6-sum
    r += __shfl_down_sync(0xFFFFFFFFu, s, 6);             // 7-sum
    return r;
}

__global__ __launch_bounds__(BLOCK_T)
void ssim_warp_kernel(const float* __restrict__ gen,
                      const float* __restrict__ tgt)
{
    const int t    = threadIdx.x;
    const int lane = t & 31;
    const int w    = blockIdx.x * (BLOCK_T >> 5) + (t >> 5);

    const int frame = w / STRIPS;
    const int strip = w - frame * STRIPS;
    const int base  = strip * 26;
    const int col   = base + lane;
    const int colc  = (col < HW - 1) ? col : (HW - 1);

    const float* gp = gen + frame * FRAME + colc;
    const float* tp = tgt + frame * FRAME + colc;

    const bool own   = (lane < 26) && (col < HW);    // exclusive pixel ownership
    const bool outok = (lane < 26) && (col < OUTW);  // valid SSIM output column

    float A[7], B[7];
#pragma unroll
    for (int k = 0; k < 7; ++k) { A[k] = 0.f; B[k] = 0.f; }
    float S0 = 0.f, S1 = 0.f, S2 = 0.f, S3 = 0.f, S4 = 0.f;
    float pabs = 0.f, psq = 0.f, pssim = 0.f;

    const float inv49 = 1.0f / 49.0f;
    const float inv48 = 1.0f / 48.0f;
    const float C1p   = 1.0e-4f;   // (0.01)^2 : 255-scaling divided out
    const float C2p   = 9.0e-4f;   // (0.03)^2

    // ---- Prologue: rows 0..5 (fill vertical window, no outputs) ----
#pragma unroll
    for (int r = 0; r < 6; ++r) {
        float a = gp[r * HW];
        float b = tp[r * HW];
        if (own) {
            float d = a - b;
            pabs += fabsf(d);
            psq = fmaf(d, d, psq);
        }
        S0 += a; S1 += b;
        S2 = fmaf(a, a, S2);
        S3 = fmaf(b, b, S3);
        S4 = fmaf(a, b, S4);
        A[r] = a; B[r] = b;
    }

    // ---- Main loop: output rows 0..505 (input rows 6..511) ----
    for (int c = 0; c < 73; ++c) {
#pragma unroll
        for (int j = 0; j < 7; ++j) {
            const int orow = c * 7 + j;
            if (orow < OUTW) {                 // warp-uniform predicate
                const int r   = orow + 6;
                const int idx = (j + 6) % 7;   // compile-time ring slot (== r % 7)
                float a = gp[r * HW];
                float b = tp[r * HW];
                if (own) {
                    float d = a - b;
                    pabs += fabsf(d);
                    psq = fmaf(d, d, psq);
                }
                float ao = A[idx], bo = B[idx];
                S0 += a - ao;
                S1 += b - bo;
                S2 = fmaf(a, a, fmaf(-ao, ao, S2));
                S3 = fmaf(b, b, fmaf(-bo, bo, S3));
                S4 = fmaf(a, b, fmaf(-ao, bo, S4));
                A[idx] = a; B[idx] = b;

                // Horizontal 7-sums across lanes (valid for lanes 0..25)
                float H0 = hsum7(S0);
                float H1 = hsum7(S1);
                float H2 = hsum7(S2);
                float H3 = hsum7(S3);
                float H4 = hsum7(S4);

                float ux  = H0 * inv49;
                float uy  = H1 * inv49;
                float vx  = fmaf(-H0, ux, H2) * inv48;   // (H2 - 49 ux^2)/48
                float vy  = fmaf(-H1, uy, H3) * inv48;
                float vxy = fmaf(-H0, uy, H4) * inv48;   // (H4 - 49 ux uy)/48
                float ux2 = ux * ux;
                float uy2 = uy * uy;
                float uxy = ux * uy;
                float num = fmaf(2.f, uxy, C1p) * fmaf(2.f, vxy, C2p);
                float den = (ux2 + uy2 + C1p) * (vx + vy + C2p);
                float s   = __fdividef(num, den);
                if (outok) pssim += s;
            }
        }
    }

    // ---- Warp reduction -> scratch ----
#pragma unroll
    for (int off = 16; off; off >>= 1) {
        pabs  += __shfl_xor_sync(0xFFFFFFFFu, pabs,  off);
        psq   += __shfl_xor_sync(0xFFFFFFFFu, psq,   off);
        pssim += __shfl_xor_sync(0xFFFFFFFFu, pssim, off);
    }
    if (lane == 0) {
        g_scratch[w * 3 + 0] = pabs;
        g_scratch[w * 3 + 1] = psq;
        g_scratch[w * 3 + 2] = pssim;
    }
}

__global__ __launch_bounds__(1024)
void finalize_kernel(const float* __restrict__ genD, int nD,
                     float* __restrict__ out)
{
    __shared__ double sm[3][32];
    double a = 0.0, s = 0.0, m = 0.0;
    for (int b = threadIdx.x; b < NWARPS; b += 1024) {
        a += (double)g_scratch[b * 3 + 0];
        s += (double)g_scratch[b * 3 + 1];
        m += (double)g_scratch[b * 3 + 2];
    }
#pragma unroll
    for (int off = 16; off; off >>= 1) {
        a += __shfl_xor_sync(0xFFFFFFFFu, a, off);
        s += __shfl_xor_sync(0xFFFFFFFFu, s, off);
        m += __shfl_xor_sync(0xFFFFFFFFu, m, off);
    }
    const int wid = threadIdx.x >> 5, lane = threadIdx.x & 31;
    if (lane == 0) { sm[0][wid] = a; sm[1][wid] = s; sm[2][wid] = m; }
    __syncthreads();
    if (threadIdx.x == 0) {
        double A = 0.0, S = 0.0, M = 0.0;
#pragma unroll
        for (int ww = 0; ww < 32; ++ww) { A += sm[0][ww]; S += sm[1][ww]; M += sm[2][ww]; }
        const double Ntot = (double)NFRAMES * HW * HW;
        double L_rec  = (A + S) / Ntot;
        double L_ssim = M / ((double)NFRAMES * OUTW * OUTW);
        double sd = 0.0;
        for (int i = 0; i < nD; ++i) sd += (double)genD[i];
        double L_adv   = -sd / (double)nD;
        double L_total = L_rec + 0.01 * (1.0 - L_ssim) + 1.0e-4 * L_adv;
        out[0] = (float)L_total;
        out[1] = (float)L_rec;
        out[2] = (float)L_ssim;
        out[3] = (float)L_adv;
    }
}

extern "C" void kernel_launch(void* const* d_in, const int* in_sizes, int n_in,
                              void* d_out, int out_size)
{
    const float* gen = (const float*)d_in[0];
    const float* tgt = (const float*)d_in[1];
    const float* gD  = (const float*)d_in[2];
    float* out = (float*)d_out;

    ssim_warp_kernel<<<NBLOCKS, BLOCK_T>>>(gen, tgt);
    finalize_kernel<<<1, 1024>>>(gD, in_sizes[2], out);
}

// round 6
// speedup vs baseline: 1.6490x; 1.1643x over previous
#include <cuda_runtime.h>
#include <math.h>

// Geometry
#define NFRAMES 160
#define HW      512
#define FRAME   (HW * HW)
#define OUTW    506            // 512 - 7 + 1
#define W_IN    128            // input columns per strip (= blockDim)
#define W_OUT   122            // output columns per strip
#define STRIPS  5              // 4*122 + 18 = 506
#define NBLOCKS (NFRAMES * STRIPS)    // 800
#define SROW    144            // padded physical smem row width (floats)
#define SCH     (8 * SROW)     // per-channel smem stride (8 batched rows)

__device__ float g_scratch[NBLOCKS * 3];
__device__ unsigned int g_ctr = 0;

__global__ __launch_bounds__(128, 6)
void ssim_fused_kernel(const float* __restrict__ gen,
                       const float* __restrict__ tgt,
                       const float* __restrict__ genD, int nD,
                       float* __restrict__ out)
{
    __shared__ float S[5 * SCH + 32];   // +32 pad: run-15 slide reads overshoot harmlessly
    __shared__ float red[3][4];
    __shared__ double dred[3][4];
    __shared__ int lastFlag;

    const int t     = threadIdx.x;
    const int bid   = blockIdx.x;
    const int frame = bid / STRIPS;
    const int strip = bid - frame * STRIPS;
    const int c0    = strip * W_OUT;
    const int col   = c0 + t;
    const int cc    = (col < HW) ? col : (HW - 1);

    const float* gp = gen + frame * FRAME + cc;
    const float* tp = tgt + frame * FRAME + cc;

    const bool own   = (t < W_OUT) && (col < HW);   // exclusive pixel ownership
    const int  txEff = min(W_OUT, OUTW - c0);

    // horizontal role: jr = row within batch, run = 8-output horizontal run
    const int jr    = t >> 4;
    const int run   = t & 15;
    const int r9    = 9 * run;           // phys(8*run + k) = 9*run + k + (k>>3)
    const int physT = t + (t >> 3);      // skewed write column

    float A[8], B[8];
    float s0 = 0.f, s1 = 0.f, s2 = 0.f, s3 = 0.f, s4 = 0.f;
    float pabs = 0.f, psq = 0.f, pssim = 0.f;

    const float inv49 = 1.0f / 49.0f;
    const float inv48 = 1.0f / 48.0f;
    const float C1p   = 1.0e-4f;   // (0.01)^2 : 255-scaling divided out
    const float C2p   = 9.0e-4f;   // (0.03)^2

    // ---- Prologue: input rows 0..5 (slot r&7), slot 7 = virtual row -1 = 0 ----
    A[7] = 0.f; B[7] = 0.f;
#pragma unroll
    for (int r = 0; r < 6; ++r) {
        float a = gp[r * HW];
        float b = tp[r * HW];
        if (own) { float d = a - b; pabs += fabsf(d); psq = fmaf(d, d, psq); }
        s0 += a; s1 += b;
        s2 = fmaf(a, a, s2);
        s3 = fmaf(b, b, s3);
        s4 = fmaf(a, b, s4);
        A[r] = a; B[r] = b;
    }

    // ---- Main: 64 batches of 8 output rows ----
    for (int b = 0; b < 64; ++b) {
        const int rbase = 8 * b + 6;

        // Vertical phase: advance sliding column sums 8 rows, stage to smem
#pragma unroll
        for (int j = 0; j < 8; ++j) {
            int r  = rbase + j;
            int rc = (r < HW) ? r : (HW - 1);
            float a  = gp[rc * HW];
            float bb = tp[rc * HW];
            if (own && r < HW) { float d = a - bb; pabs += fabsf(d); psq = fmaf(d, d, psq); }
            float ao = A[(j + 7) & 7];
            float bo = B[(j + 7) & 7];
            s0 += a - ao;
            s1 += bb - bo;
            s2 = fmaf(a, a,  fmaf(-ao, ao, s2));
            s3 = fmaf(bb, bb, fmaf(-bo, bo, s3));
            s4 = fmaf(a, bb, fmaf(-ao, bo, s4));
            A[(6 + j) & 7] = a;
            B[(6 + j) & 7] = bb;
            int so = j * SROW + physT;
            S[0 * SCH + so] = s0;
            S[1 * SCH + so] = s1;
            S[2 * SCH + so] = s2;
            S[3 * SCH + so] = s3;
            S[4 * SCH + so] = s4;
        }
        __syncthreads();

        // Horizontal phase: each thread = (row jr, 8-output run)
        {
            const int orow = 8 * b + jr;
            if ((8 * run < txEff) && (orow < OUTW)) {
                const float* p0 = S + 0 * SCH + jr * SROW + r9;
                const float* p1 = S + 1 * SCH + jr * SROW + r9;
                const float* p2 = S + 2 * SCH + jr * SROW + r9;
                const float* p3 = S + 3 * SCH + jr * SROW + r9;
                const float* p4 = S + 4 * SCH + jr * SROW + r9;

                float H0 = 0.f, H1 = 0.f, H2 = 0.f, H3 = 0.f, H4 = 0.f;
#pragma unroll
                for (int k = 0; k < 7; ++k) {      // phys offset = k for k<=6
                    H0 += p0[k]; H1 += p1[k]; H2 += p2[k]; H3 += p3[k]; H4 += p4[k];
                }
#pragma unroll
                for (int s = 0; s < 8; ++s) {
                    if (s > 0) {
                        const int ca = 6 + s;                  // add col (compile-time fold)
                        const int oa = ca + (ca >> 3);
                        const int os = s - 1;                  // sub col, phys = s-1
                        H0 += p0[oa] - p0[os];
                        H1 += p1[oa] - p1[os];
                        H2 += p2[oa] - p2[os];
                        H3 += p3[oa] - p3[os];
                        H4 += p4[oa] - p4[os];
                    }
                    if (8 * run + s < txEff) {
                        float ux  = H0 * inv49;
                        float uy  = H1 * inv49;
                        float vx  = fmaf(-H0, ux, H2) * inv48;
                        float vy  = fmaf(-H1, uy, H3) * inv48;
                        float vxy = fmaf(-H0, uy, H4) * inv48;
                        float ux2 = ux * ux;
                        float uy2 = uy * uy;
                        float uxy = ux * uy;
                        float num = fmaf(2.f, uxy, C1p) * fmaf(2.f, vxy, C2p);
                        float den = (ux2 + uy2 + C1p) * (vx + vy + C2p);
                        pssim += __fdividef(num, den);
                    }
                }
            }
        }
        __syncthreads();   // protect S before next batch overwrites
    }

    // ---- Block reduction -> scratch ----
#pragma unroll
    for (int off = 16; off; off >>= 1) {
        pabs  += __shfl_xor_sync(0xFFFFFFFFu, pabs,  off);
        psq   += __shfl_xor_sync(0xFFFFFFFFu, psq,   off);
        pssim += __shfl_xor_sync(0xFFFFFFFFu, pssim, off);
    }
    const int wid = t >> 5, lane = t & 31;
    if (lane == 0) { red[0][wid] = pabs; red[1][wid] = psq; red[2][wid] = pssim; }
    __syncthreads();
    if (t == 0) {
        float a = red[0][0] + red[0][1] + red[0][2] + red[0][3];
        float s = red[1][0] + red[1][1] + red[1][2] + red[1][3];
        float m = red[2][0] + red[2][1] + red[2][2] + red[2][3];
        g_scratch[bid * 3 + 0] = a;
        g_scratch[bid * 3 + 1] = s;
        g_scratch[bid * 3 + 2] = m;
        __threadfence();
        unsigned int v = atomicAdd(&g_ctr, 1u);
        lastFlag = (v == NBLOCKS - 1);
    }
    __syncthreads();

    // ---- Last block: final reduction + loss assembly ----
    if (lastFlag) {
        __threadfence();
        double a = 0.0, s = 0.0, m = 0.0;
        for (int i = t; i < NBLOCKS; i += 128) {
            a += (double)__ldcg(&g_scratch[3 * i + 0]);
            s += (double)__ldcg(&g_scratch[3 * i + 1]);
            m += (double)__ldcg(&g_scratch[3 * i + 2]);
        }
#pragma unroll
        for (int off = 16; off; off >>= 1) {
            a += __shfl_xor_sync(0xFFFFFFFFu, a, off);
            s += __shfl_xor_sync(0xFFFFFFFFu, s, off);
            m += __shfl_xor_sync(0xFFFFFFFFu, m, off);
        }
        if (lane == 0) { dred[0][wid] = a; dred[1][wid] = s; dred[2][wid] = m; }
        __syncthreads();
        if (t == 0) {
            double A = dred[0][0] + dred[0][1] + dred[0][2] + dred[0][3];
            double Sq = dred[1][0] + dred[1][1] + dred[1][2] + dred[1][3];
            double M = dred[2][0] + dred[2][1] + dred[2][2] + dred[2][3];
            const double Ntot = (double)NFRAMES * HW * HW;
            double L_rec  = (A + Sq) / Ntot;
            double L_ssim = M / ((double)NFRAMES * OUTW * OUTW);
            double sd = 0.0;
            for (int i = 0; i < nD; ++i) sd += (double)genD[i];
            double L_adv   = -sd / (double)nD;
            double L_total = L_rec + 0.01 * (1.0 - L_ssim) + 1.0e-4 * L_adv;
            out[0] = (float)L_total;
            out[1] = (float)L_rec;
            out[2] = (float)L_ssim;
            out[3] = (float)L_adv;
            g_ctr = 0;   // reset for next graph replay
        }
    }
}

extern "C" void kernel_launch(void* const* d_in, const int* in_sizes, int n_in,
                              void* d_out, int out_size)
{
    const float* gen = (const float*)d_in[0];
    const float* tgt = (const float*)d_in[1];
    const float* gD  = (const float*)d_in[2];
    float* out = (float*)d_out;

    ssim_fused_kernel<<<NBLOCKS, 128>>>(gen, tgt, gD, in_sizes[2], out);
}

// round 7
// speedup vs baseline: 3.3777x; 2.0483x over previous
#include <cuda_runtime.h>
#include <math.h>

// Geometry
#define NFRAMES 160
#define HW      512
#define FRAME   (HW * HW)
#define OUTW    506            // 512 - 7 + 1
#define W_IN    128            // input columns per strip (= blockDim)
#define W_OUT   122            // output columns per strip
#define STRIPS  5              // 4*122 + 18 = 506
#define NBLOCKS (NFRAMES * STRIPS)    // 800
#define SROW    152            // padded physical smem row width (float2 units)

__device__ float g_scratch[NBLOCKS * 3];
__device__ unsigned int g_ctr = 0;

__global__ __launch_bounds__(128, 8)
void ssim_fused_kernel(const float* __restrict__ gen,
                       const float* __restrict__ tgt,
                       const float* __restrict__ genD, int nD,
                       float* __restrict__ out)
{
    // Channel pairs: SPQ = (sum p, sum q), SP2 = (sum p^2, sum q^2); p=a+b, q=a-b
    __shared__ float2 SPQ[8 * SROW];
    __shared__ float2 SP2[8 * SROW];
    __shared__ float red[3][4];
    __shared__ double dred[3][4];
    __shared__ int lastFlag;

    const int t     = threadIdx.x;
    const int bid   = blockIdx.x;
    const int frame = bid / STRIPS;
    const int strip = bid - frame * STRIPS;
    const int c0    = strip * W_OUT;
    const int col   = c0 + t;
    const int cc    = (col < HW) ? col : (HW - 1);

    const float* gp = gen + frame * FRAME + cc;
    const float* tp = tgt + frame * FRAME + cc;

    const bool own   = (t < W_OUT) && (col < HW);   // exclusive pixel ownership
    const int  txEff = min(W_OUT, OUTW - c0);

    // horizontal role: jr = row within batch (0..7), run = 8-output horizontal run (0..15)
    const int jr        = t >> 4;
    const int run       = t & 15;
    const bool runActive = (8 * run) < txEff;
    const int physT     = t + (t >> 3);     // skewed write column
    // phys(8*run + k) = 9*run + k + (k>>3)

    float Pr[8], Qr[8];                     // vertical ring of (p, q)
    float sp = 0.f, sq = 0.f, sp2 = 0.f, sq2 = 0.f;
    float pabs = 0.f, psq = 0.f, pssim = 0.f;

    const float inv49 = 1.0f / 49.0f;
    const float k1    = 1.0f / 4802.0f;     // 1/(2*49^2)
    const float inv96 = 1.0f / 96.0f;       // 1/(2*48)
    const float C1p   = 1.0e-4f;            // (0.01)^2 : 255-scaling divided out
    const float C2p   = 9.0e-4f;            // (0.03)^2

    // ---- Prologue: input rows 0..5; slot 7 = virtual row -1 = 0 ----
    Pr[7] = 0.f; Qr[7] = 0.f;
#pragma unroll
    for (int r = 0; r < 6; ++r) {
        float a = gp[r * HW];
        float b = tp[r * HW];
        float p = a + b, q = a - b;
        if (own) { pabs += fabsf(q); psq = fmaf(q, q, psq); }
        sp += p; sq += q;
        sp2 = fmaf(p, p, sp2);
        sq2 = fmaf(q, q, sq2);
        Pr[r] = p; Qr[r] = q;
    }

    // ---- Main: 64 batches of 8 output rows ----
    for (int b = 0; b < 64; ++b) {
        const int rbase = 8 * b + 6;

        // Vertical: advance sliding column sums 8 rows, stage pairs to smem
#pragma unroll
        for (int j = 0; j < 8; ++j) {
            int r  = rbase + j;
            int rc = (r < HW) ? r : (HW - 1);
            float a  = gp[rc * HW];
            float bb = tp[rc * HW];
            float p = a + bb, q = a - bb;
            if (own && r < HW) { pabs += fabsf(q); psq = fmaf(q, q, psq); }
            float po = Pr[(j + 7) & 7];
            float qo = Qr[(j + 7) & 7];
            sp += p - po;
            sq += q - qo;
            sp2 = fmaf(p, p, fmaf(-po, po, sp2));
            sq2 = fmaf(q, q, fmaf(-qo, qo, sq2));
            Pr[(6 + j) & 7] = p;
            Qr[(6 + j) & 7] = q;
            int so = j * SROW + physT;
            SPQ[so] = make_float2(sp, sq);
            SP2[so] = make_float2(sp2, sq2);
        }
        __syncthreads();

        // Horizontal: thread = (row jr, 8-output run); sliding windows + ratio tree
        {
            const int orow = 8 * b + jr;
            if (runActive && orow < OUTW) {
                const float2* rPQ = SPQ + jr * SROW + 9 * run;
                const float2* rP2 = SP2 + jr * SROW + 9 * run;

                float Pw = 0.f, Qw = 0.f, P2w = 0.f, Q2w = 0.f;
#pragma unroll
                for (int k = 0; k < 7; ++k) {      // phys offset = k for k<=6
                    float2 v = rPQ[k];
                    float2 u = rP2[k];
                    Pw += v.x; Qw += v.y;
                    P2w += u.x; Q2w += u.y;
                }

                float N = 0.f, D = 1.f;
#pragma unroll
                for (int s = 0; s < 8; ++s) {
                    if (s > 0) {
                        const int oa = (s + 6) + ((s + 6) >> 3);   // add col (folded)
                        const int os = s - 1;                      // sub col, phys = s-1
                        float2 nv = rPQ[oa], ov = rPQ[os];
                        float2 n2 = rP2[oa], o2 = rP2[os];
                        Pw  += nv.x - ov.x;  Qw  += nv.y - ov.y;
                        P2w += n2.x - o2.x;  Q2w += n2.y - o2.y;
                    }
                    float Psq  = Pw * Pw;
                    float Qsq  = Qw * Qw;
                    float sum2 = Psq + Qsq;
                    float dif2 = Psq - Qsq;
                    float A2   = P2w + Q2w;
                    float B2   = P2w - Q2w;
                    float num1 = fmaf(k1, dif2, C1p);                          // 2 ux uy + C1
                    float denu = fmaf(k1, sum2, C1p);                          // ux^2+uy^2 + C1
                    float denv = fmaf(inv96, fmaf(-inv49, sum2, A2), C2p);     // vx+vy + C2
                    float num2 = fmaf(inv96, fmaf(-inv49, dif2, B2), C2p);     // 2 vxy + C2
                    float n = num1 * num2;
                    float d = denu * denv;
                    bool v  = (8 * run + s) < txEff;
                    n = v ? n : 0.f;
                    d = v ? d : 1.f;
                    if (s == 0) { N = n; D = d; }
                    else        { N = fmaf(N, d, n * D); D *= d; }
                }
                pssim += __fdividef(N, D);   // one MUFU per 8 outputs
            }
        }
        __syncthreads();   // protect S before next batch overwrites
    }

    // ---- Block reduction -> scratch ----
#pragma unroll
    for (int off = 16; off; off >>= 1) {
        pabs  += __shfl_xor_sync(0xFFFFFFFFu, pabs,  off);
        psq   += __shfl_xor_sync(0xFFFFFFFFu, psq,   off);
        pssim += __shfl_xor_sync(0xFFFFFFFFu, pssim, off);
    }
    const int wid = t >> 5, lane = t & 31;
    if (lane == 0) { red[0][wid] = pabs; red[1][wid] = psq; red[2][wid] = pssim; }
    __syncthreads();
    if (t == 0) {
        float a = red[0][0] + red[0][1] + red[0][2] + red[0][3];
        float s = red[1][0] + red[1][1] + red[1][2] + red[1][3];
        float m = red[2][0] + red[2][1] + red[2][2] + red[2][3];
        g_scratch[bid * 3 + 0] = a;
        g_scratch[bid * 3 + 1] = s;
        g_scratch[bid * 3 + 2] = m;
        __threadfence();
        unsigned int v = atomicAdd(&g_ctr, 1u);
        lastFlag = (v == NBLOCKS - 1);
    }
    __syncthreads();

    // ---- Last block: final reduction + loss assembly ----
    if (lastFlag) {
        __threadfence();
        double a = 0.0, s = 0.0, m = 0.0;
        for (int i = t; i < NBLOCKS; i += 128) {
            a += (double)__ldcg(&g_scratch[3 * i + 0]);
            s += (double)__ldcg(&g_scratch[3 * i + 1]);
            m += (double)__ldcg(&g_scratch[3 * i + 2]);
        }
#pragma unroll
        for (int off = 16; off; off >>= 1) {
            a += __shfl_xor_sync(0xFFFFFFFFu, a, off);
            s += __shfl_xor_sync(0xFFFFFFFFu, s, off);
            m += __shfl_xor_sync(0xFFFFFFFFu, m, off);
        }
        if (lane == 0) { dred[0][wid] = a; dred[1][wid] = s; dred[2][wid] = m; }
        __syncthreads();
        if (t == 0) {
            double A  = dred[0][0] + dred[0][1] + dred[0][2] + dred[0][3];
            double Sq = dred[1][0] + dred[1][1] + dred[1][2] + dred[1][3];
            double M  = dred[2][0] + dred[2][1] + dred[2][2] + dred[2][3];
            const double Ntot = (double)NFRAMES * HW * HW;
            double L_rec  = (A + Sq) / Ntot;
            double L_ssim = M / ((double)NFRAMES * OUTW * OUTW);
            double sd = 0.0;
            for (int i = 0; i < nD; ++i) sd += (double)genD[i];
            double L_adv   = -sd / (double)nD;
            double L_total = L_rec + 0.01 * (1.0 - L_ssim) + 1.0e-4 * L_adv;
            out[0] = (float)L_total;
            out[1] = (float)L_rec;
            out[2] = (float)L_ssim;
            out[3] = (float)L_adv;
            g_ctr = 0;   // reset for next graph replay
        }
    }
}

extern "C" void kernel_launch(void* const* d_in, const int* in_sizes, int n_in,
                              void* d_out, int out_size)
{
    const float* gen = (const float*)d_in[0];
    const float* tgt = (const float*)d_in[1];
    const float* gD  = (const float*)d_in[2];
    float* out = (float*)d_out;

    ssim_fused_kernel<<<NBLOCKS, 128>>>(gen, tgt, gD, in_sizes[2], out);
}